// round 10
// baseline (speedup 1.0000x reference)
#include <cuda_runtime.h>
#include <cuda_bf16.h>
#include <cstdint>

// ---------------- problem constants ----------------
#define NBINS       64
#define KDIM        192
#define FC          64
#define TILE_P      64
#define NTHREADS    256
#define MCAP        100000
#define Z_MIN_F     (-3.0f)
#define INV_BIN     16.0f
#define EPS_MEAN    1e-5f
#define EPS_BN      1e-5f

// ---- shared layout (float offsets) ----
// At  [64][192] swizzled mma A operand   12288 (48KB)
// Wt  [64][192] swizzled mma B operand   12288 (48KB)
// stg ring of 3 x [64 pillars x 9 float2] = 3456 floats (13.5KB)
#define SM_AT    0
#define SM_W     12288
#define SM_STG   24576
#define STG_BUF  1152                      // floats per ring buffer
#define SMEM_FLOATS (SM_STG + 3 * STG_BUF)
#define SMEM_BYTES  (SMEM_FLOATS * 4)      // 112128 B -> 2 CTAs/SM (219KB)

// ---------------- global scratch ----------------
__device__ float4 g_X[MCAP * (FC / 4)];
__device__ float  g_sum[FC];
__device__ float  g_sqs[FC];
__device__ float  g_scale[FC];
__device__ float  g_shift[FC];

__device__ __forceinline__ float round_tf32(float x) {
    uint32_t u;
    asm("cvt.rna.tf32.f32 %0, %1;" : "=r"(u) : "f"(x));
    return __uint_as_float(u);
}
__device__ __forceinline__ uint32_t smem_u32(const void* p) {
    uint32_t a;
    asm("{ .reg .u64 t; cvta.to.shared.u64 t, %1; cvt.u32.u64 %0, t; }" : "=r"(a) : "l"(p));
    return a;
}
__device__ __forceinline__ void cp8(uint32_t saddr, const void* g) {
    asm volatile("cp.async.ca.shared.global [%0], [%1], 8;" :: "r"(saddr), "l"(g) : "memory");
}
__device__ __forceinline__ void cp_commit() {
    asm volatile("cp.async.commit_group;" ::: "memory");
}
__device__ __forceinline__ void cp_wait1() {
    asm volatile("cp.async.wait_group 1;" ::: "memory");
}

__device__ __forceinline__ void mma8(float* d, uint32_t a0, uint32_t a1,
                                     uint32_t a2, uint32_t a3,
                                     uint32_t b0, uint32_t b1) {
    asm volatile(
        "mma.sync.aligned.m16n8k8.row.col.f32.tf32.tf32.f32 "
        "{%0,%1,%2,%3}, {%4,%5,%6,%7}, {%8,%9}, {%0,%1,%2,%3};"
        : "+f"(d[0]), "+f"(d[1]), "+f"(d[2]), "+f"(d[3])
        : "r"(a0), "r"(a1), "r"(a2), "r"(a3), "r"(b0), "r"(b1));
}

// ---------------- kernel 1: persistent hist + tf32 mma GEMM + fused BN ----------------
__global__ void __launch_bounds__(NTHREADS, 2)
main_kernel(const float* __restrict__ feat,
            const int*   __restrict__ nump,
            const float* __restrict__ W,
            const float* __restrict__ bbias,
            int M, int ntiles)
{
    extern __shared__ float sm[];
    float* At   = sm + SM_AT;
    float* Wt   = sm + SM_W;
    float* stgf = sm + SM_STG;
    const uint32_t stg_b = smem_u32(sm) + SM_STG * 4;

    const int tid = threadIdx.x;

    // ---- one-time: stage W (tf32-rounded, swizzled cols) ----
    {
        const float4* W4 = (const float4*)W;
        #pragma unroll
        for (int i = tid; i < (FC * KDIM) / 4; i += NTHREADS) {
            float4 v = W4[i];
            int c  = i / 48;
            int k4 = (i - c * 48) * 4;
            v.x = round_tf32(v.x); v.y = round_tf32(v.y);
            v.z = round_tf32(v.z); v.w = round_tf32(v.w);
            int colp = k4 ^ ((c & 7) << 2);
            *(float4*)(Wt + c * 192 + colp) = v;
        }
    }

    // GEMM geometry: 8 warps = 4 pillar-groups x 2 n-halves
    const int lane  = tid & 31;
    const int wid   = tid >> 5;
    const int nhalf = wid >> 2;
    const int wpg   = wid & 3;
    const int gid   = lane >> 2;
    const int tig   = lane & 3;
    const int gswz  = gid << 2;
    const int p0    = wpg * 16;
    const int cb    = nhalf * 32;

    float2 bias2[4];
    #pragma unroll
    for (int j = 0; j < 4; j++)
        bias2[j] = *(const float2*)(bbias + cb + j * 8 + 2 * tig);

    float2 s2[4], q2[4];
    #pragma unroll
    for (int j = 0; j < 4; j++) {
        s2[j] = make_float2(0.f, 0.f);
        q2[j] = make_float2(0.f, 0.f);
    }

    // staging: element e = tid + u*256 (u=0,1) -> pillar e>>3 (0..63), point e&7
    const int spb = tid >> 3;          // pillar base (u=0); +32 for u=1
    const int pt  = tid & 7;

    // histogram: 4 threads per pillar, each owns a 16-bin quarter
    const int hp   = tid & 63;         // pillar
    const int hq   = tid >> 6;         // quarter 0..3 -> bins [16q,16q+16)
    const int hswz = (hp & 7) << 2;
    float* hrow = At + hp * 192;

    int np_cur[2] = {0, 0};
    int np_nxt[2] = {0, 0};
    int isl = 0;                       // ring slot of next issued chunk
    int csl = 0;                       // ring slot of next consumed chunk

    // ---- prime: first tile's chunks 0,1 ----
    const int tile0 = blockIdx.x;
    if (tile0 < ntiles) {
        const int b0 = tile0 * TILE_P;
        #pragma unroll
        for (int u = 0; u < 2; u++) {
            int gp = b0 + spb + u * 32;
            np_cur[u] = (gp < M) ? nump[gp] : 0;
        }
        #pragma unroll
        for (int c0 = 0; c0 < 2; c0++) {
            #pragma unroll
            for (int u = 0; u < 2; u++) {
                int p = spb + u * 32;
                if (np_cur[u] > c0 * 8)
                    cp8(stg_b + isl * (STG_BUF * 4) + (p * 9 + pt) * 8,
                        feat + (size_t)(b0 + p) * 256 + c0 * 32 + pt * 4 + 2);
            }
            cp_commit();
            isl = (isl + 1 < 3) ? isl + 1 : 0;
        }
    }

    for (int tile = tile0; tile < ntiles; tile += gridDim.x) {
        const int base = tile * TILE_P;
        const int nxt  = tile + gridDim.x;
        const int nbase = nxt * TILE_P;

        const int npt = (base + hp < M) ? nump[base + hp] : 0;

        __syncthreads();               // At reusable (prev GEMM done)
        // zero At while cp.asyncs fly
        {
            float4 z4 = make_float4(0.f, 0.f, 0.f, 0.f);
            float4* A4 = (float4*)At;
            #pragma unroll
            for (int i = tid; i < (TILE_P * KDIM) / 4; i += NTHREADS) A4[i] = z4;
        }

        // ---- 8 chunk phases, continuous ring-3 pipeline ----
        #pragma unroll
        for (int ch = 0; ch < 8; ch++) {
            if (ch == 0) {             // prefetch next tile's num_points early
                #pragma unroll
                for (int u = 0; u < 2; u++) {
                    int gp = nbase + spb + u * 32;
                    np_nxt[u] = (nxt < ntiles && gp < M) ? nump[gp] : 0;
                }
            }
            cp_wait1();                // chunk ch resident
            __syncthreads();
            // issue next chunk in sequence (ch+2 of this tile, or 0/1 of next)
            {
                const int  cn    = (ch < 6) ? (ch + 2) : (ch - 6);
                const int  tbase = (ch < 6) ? base : nbase;
                const int* np    = (ch < 6) ? np_cur : np_nxt;
                #pragma unroll
                for (int u = 0; u < 2; u++) {
                    int p = spb + u * 32;
                    if (np[u] > cn * 8)
                        cp8(stg_b + isl * (STG_BUF * 4) + (p * 9 + pt) * 8,
                            feat + (size_t)(tbase + p) * 256 + cn * 32 + pt * 4 + 2);
                }
                cp_commit();
                isl = (isl + 1 < 3) ? isl + 1 : 0;
            }
            // histogram chunk ch: 4 threads/pillar, disjoint bin quarters
            {
                const float2* buf = (const float2*)(stgf + csl * STG_BUF);
                csl = (csl + 1 < 3) ? csl + 1 : 0;
                #pragma unroll
                for (int j = 0; j < 8; j++) {
                    if (ch * 8 + j < npt) {
                        float2 v = buf[hp * 9 + j];
                        float z = v.x, r = v.y;
                        int bin = (int)((z - Z_MIN_F) * INV_BIN);
                        bin = max(0, min(NBINS - 1, bin));
                        if ((bin >> 4) == hq) {
                            int k3 = 3 * bin;
                            float* pc = hrow + ((k3)     ^ hswz);
                            float* pz = hrow + ((k3 + 1) ^ hswz);
                            float* pr = hrow + ((k3 + 2) ^ hswz);
                            float c0 = *pc;
                            float s0 = *pz;
                            float r0 = *pr;
                            *pc = c0 + 1.0f;
                            *pz = s0 + z;
                            *pr = r0 + r;
                        }
                    }
                }
            }
        }
        np_cur[0] = np_nxt[0];
        np_cur[1] = np_nxt[1];
        __syncthreads();               // At complete

        // ---- sums -> means, tf32-rounded ----
        #pragma unroll
        for (int idx = tid; idx < TILE_P * NBINS; idx += NTHREADS) {
            int bin = idx & 63;
            int p   = idx >> 6;
            int swz = (p & 7) << 2;
            float* row = At + p * 192;
            int k3 = 3 * bin;
            float* pc = row + ((k3)     ^ swz);
            float* pz = row + ((k3 + 1) ^ swz);
            float* pr = row + ((k3 + 2) ^ swz);
            float inv = __frcp_rn(*pc + EPS_MEAN);
            *pz = round_tf32(*pz * inv);
            *pr = round_tf32(*pr * inv);
        }
        __syncthreads();

        // ---- GEMM: warp = m16 (p0..p0+15) x n32 (cb..cb+31) ----
        float d[4][4];
        #pragma unroll
        for (int j = 0; j < 4; j++) {
            d[j][0] = bias2[j].x; d[j][1] = bias2[j].y;
            d[j][2] = bias2[j].x; d[j][3] = bias2[j].y;
        }
        {
            const float* Ar0 = At + (p0 + gid) * 192;
            const float* Ar1 = Ar0 + 8 * 192;
            const float* Wg  = Wt + (cb + gid) * 192;
            #pragma unroll 4
            for (int s = 0; s < 24; s++) {
                int col  = ((s << 3) | tig) ^ gswz;
                int colx = col ^ 4;
                uint32_t a0 = __float_as_uint(Ar0[col]);
                uint32_t a1 = __float_as_uint(Ar1[col]);
                uint32_t a2 = __float_as_uint(Ar0[colx]);
                uint32_t a3 = __float_as_uint(Ar1[colx]);
                #pragma unroll
                for (int j = 0; j < 4; j++) {
                    const float* wr = Wg + j * (8 * 192);
                    uint32_t b0 = __float_as_uint(wr[col]);
                    uint32_t b1 = __float_as_uint(wr[colx]);
                    mma8(d[j], a0, a1, a2, a3, b0, b1);
                }
            }
        }

        // ---- epilogue: store x + BN register accumulation ----
        {
            int gp0 = base + p0 + gid;
            int gp1 = gp0 + 8;
            float2* gx = (float2*)g_X;
            int co = nhalf * 16;
            if (gp0 < M) {
                #pragma unroll
                for (int j = 0; j < 4; j++) {
                    gx[gp0 * 32 + co + j * 4 + tig] = make_float2(d[j][0], d[j][1]);
                    s2[j].x += d[j][0]; s2[j].y += d[j][1];
                    q2[j].x += d[j][0] * d[j][0];
                    q2[j].y += d[j][1] * d[j][1];
                }
            }
            if (gp1 < M) {
                #pragma unroll
                for (int j = 0; j < 4; j++) {
                    gx[gp1 * 32 + co + j * 4 + tig] = make_float2(d[j][2], d[j][3]);
                    s2[j].x += d[j][2]; s2[j].y += d[j][3];
                    q2[j].x += d[j][2] * d[j][2];
                    q2[j].y += d[j][3] * d[j][3];
                }
            }
        }
    }

    // ---- final BN reduction: regs -> smem -> global atomics ----
    __syncthreads();
    float2* Ssm = (float2*)sm;         // At region dead
    float2* Qsm = Ssm + 1024;
    #pragma unroll
    for (int j = 0; j < 4; j++) {
        Ssm[tid * 4 + j] = s2[j];
        Qsm[tid * 4 + j] = q2[j];
    }
    __syncthreads();
    if (tid < FC) {
        int c  = tid;
        int nh = c >> 5;
        int jj = (c & 31) >> 3;
        int tg = (c >> 1) & 3;
        int e  = c & 1;
        float ts = 0.f, tq = 0.f;
        #pragma unroll
        for (int w = 0; w < 4; w++) {          // wpg
            #pragma unroll
            for (int g = 0; g < 8; g++) {      // gid
                int src = (((nh * 4 + w) << 5) + (g << 2) + tg) * 4 + jj;
                float2 vs = Ssm[src];
                float2 vq = Qsm[src];
                ts += e ? vs.y : vs.x;
                tq += e ? vq.y : vq.x;
            }
        }
        atomicAdd(&g_sum[c], ts);
        atomicAdd(&g_sqs[c], tq);
    }
}

// ---------------- kernel 2: finalize BN scale/shift ----------------
__global__ void finalize_kernel(const float* __restrict__ gamma,
                                const float* __restrict__ beta,
                                int M)
{
    int c = threadIdx.x;
    if (c < FC) {
        float invM = 1.0f / (float)M;
        float mu   = g_sum[c] * invM;
        float var  = g_sqs[c] * invM - mu * mu;
        var = fmaxf(var, 0.0f);
        float sc = gamma[c] * rsqrtf(var + EPS_BN);
        g_scale[c] = sc;
        g_shift[c] = beta[c] - mu * sc;
    }
}

// ---------------- kernel 3: normalize + ReLU + reset accumulators ----------------
__global__ void __launch_bounds__(256)
apply_kernel(float4* __restrict__ out, int M)
{
    int n4 = M * (FC / 4);
    int gid = blockIdx.x * blockDim.x + threadIdx.x;
    int stride = gridDim.x * blockDim.x;

    float4 x[4];
    int idx[4];
    #pragma unroll
    for (int u = 0; u < 4; u++) {
        int i = gid + u * stride;
        idx[u] = i;
        if (i < n4) x[u] = g_X[i];
    }
    #pragma unroll
    for (int u = 0; u < 4; u++) {
        int i = idx[u];
        if (i < n4) {
            int cbq = (i & 15) * 4;
            float4 sc = *(const float4*)&g_scale[cbq];
            float4 sh = *(const float4*)&g_shift[cbq];
            float4 r;
            r.x = fmaxf(fmaf(x[u].x, sc.x, sh.x), 0.0f);
            r.y = fmaxf(fmaf(x[u].y, sc.y, sh.y), 0.0f);
            r.z = fmaxf(fmaf(x[u].z, sc.z, sh.z), 0.0f);
            r.w = fmaxf(fmaf(x[u].w, sc.w, sh.w), 0.0f);
            out[i] = r;
        }
    }
    if (blockIdx.x == 0 && threadIdx.x < FC) {
        g_sum[threadIdx.x] = 0.0f;
        g_sqs[threadIdx.x] = 0.0f;
    }
}

// ---------------- launch ----------------
extern "C" void kernel_launch(void* const* d_in, const int* in_sizes, int n_in,
                              void* d_out, int out_size)
{
    const float* feat  = (const float*)d_in[0];
    const int*   nump  = (const int*)  d_in[1];
    const float* W     = (const float*)d_in[3];
    const float* bbias = (const float*)d_in[4];
    const float* gamma = (const float*)d_in[5];
    const float* beta  = (const float*)d_in[6];
    float4* out = (float4*)d_out;

    int M = in_sizes[1];
    if (M > MCAP) M = MCAP;
    int ntiles = (M + TILE_P - 1) / TILE_P;

    cudaFuncSetAttribute(main_kernel, cudaFuncAttributeMaxDynamicSharedMemorySize, SMEM_BYTES);

    int grid = ntiles < 296 ? ntiles : 296;     // 2 CTAs per SM
    main_kernel<<<grid, NTHREADS, SMEM_BYTES>>>(feat, nump, W, bbias, M, ntiles);
    finalize_kernel<<<1, 64>>>(gamma, beta, M);
    int n4 = M * (FC / 4);
    int blocks = ((n4 + 3) / 4 + 255) / 256;
    apply_kernel<<<blocks, 256>>>(out, M);
}